// round 5
// baseline (speedup 1.0000x reference)
#include <cuda_runtime.h>

// ConstrainLoss: spatial-softmax moment loss.
// x: (B=256, 13, 13, C=1024) fp32. Output: scalar fp32.
//
// Per (b,h,w): f = softmax_c(x). Per (b,c): S0,S1x,S2x,S1y,S2y over 169 positions.
// var_x = (S2x - 2 mx S1x + mx^2 S0) / (169 (S0+eps)), mx = S1x/(S0+eps); same for y.
// det = (vx+vy)^2 * Z ; out = sum over (b,c) / (B*C).

#define CCH    1024
#define HWD    13
#define NCHUNK 4
#define BMAX   256

// Scratch: per-chunk partial moments [chunk][b][moment][c] (~21 MB) + per-b sums.
__device__ float g_mom[NCHUNK][BMAX][5][CCH];
__device__ float g_partial[BMAX];

__device__ __forceinline__ float warp_sum(float v) {
    v += __shfl_xor_sync(0xffffffffu, v, 16);
    v += __shfl_xor_sync(0xffffffffu, v, 8);
    v += __shfl_xor_sync(0xffffffffu, v, 4);
    v += __shfl_xor_sync(0xffffffffu, v, 2);
    v += __shfl_xor_sync(0xffffffffu, v, 1);
    return v;
}

// ---------------------------------------------------------------------------
// Kernel 1: per-(b, row-chunk) moment accumulation.
// grid = (B, 4); block = 1024 threads (thread == channel).
// chunk 0 -> rows 0..3, chunks 1..3 -> 3 rows each.
// ---------------------------------------------------------------------------
__global__ __launch_bounds__(CCH, 1)
void moments_kernel(const float* __restrict__ x) {
    const int b     = blockIdx.x;
    const int chunk = blockIdx.y;
    const int h0    = (chunk == 0) ? 0 : (1 + 3 * chunk);   // 0,4,7,10
    const int nrows = (chunk == 0) ? 4 : 3;
    const int c     = threadIdx.x;
    const int warp  = c >> 5;
    const int lane  = c & 31;

    __shared__ float red[HWD][32];   // per-position warp partials
    __shared__ float s_inv[HWD];     // per-position 1/sum(exp)

    float s0 = 0.f, s1x = 0.f, s2x = 0.f, s1y = 0.f, s2y = 0.f;

    for (int r = 0; r < nrows; ++r) {
        const int h = h0 + r;
        const float* p = x + (((size_t)b * HWD + h) * HWD) * CCH + c;

        // 13 independent coalesced loads -> exp (no max-subtract needed: |x|<~6)
        float e[HWD];
#pragma unroll
        for (int w = 0; w < HWD; ++w)
            e[w] = __expf(__ldg(p + (size_t)w * CCH));

        // Phase 1: warp-level sums for all 13 positions (interleaved shuffles)
#pragma unroll
        for (int w = 0; w < HWD; ++w) {
            float v = warp_sum(e[w]);
            if (lane == 0) red[w][warp] = v;
        }
        __syncthreads();

        // Phase 2: warps 0..12 each finish one position, store reciprocal
        if (warp < HWD) {
            float v = warp_sum(red[warp][lane]);
            if (lane == 0) s_inv[warp] = __frcp_rn(v);
        }
        __syncthreads();

        // Phase 3: accumulate moments. yv = w+1 are compile-time immediates,
        // xv is row-constant -> folded out of the inner loop.
        float r0 = 0.f, r1y = 0.f, r2y = 0.f;
#pragma unroll
        for (int w = 0; w < HWD; ++w) {
            const float g  = e[w] * s_inv[w];
            const float yv = (float)(w + 1);
            r0  += g;
            r1y  = fmaf(yv, g, r1y);
            r2y  = fmaf(yv * yv, g, r2y);
        }
        const float xv = (float)(h + 1);
        s0  += r0;
        s1x  = fmaf(xv, r0, s1x);
        s2x  = fmaf(xv * xv, r0, s2x);
        s1y += r1y;
        s2y += r2y;
        // red/s_inv reuse next iteration is safe: all reads complete before the
        // second barrier above; next iteration's writes come after it.
    }

    float* out = &g_mom[chunk][b][0][0];
    out[0 * CCH + c] = s0;
    out[1 * CCH + c] = s1x;
    out[2 * CCH + c] = s2x;
    out[3 * CCH + c] = s1y;
    out[4 * CCH + c] = s2y;
}

// ---------------------------------------------------------------------------
// Kernel 2: combine chunks, compute det per (b,c), reduce over c.
// grid = B, block = 1024.
// ---------------------------------------------------------------------------
__global__ __launch_bounds__(CCH)
void combine_kernel() {
    const int b = blockIdx.x;
    const int c = threadIdx.x;

    float m0 = 0.f, m1 = 0.f, m2 = 0.f, m3 = 0.f, m4 = 0.f;
#pragma unroll
    for (int k = 0; k < NCHUNK; ++k) {
        m0 += g_mom[k][b][0][c];
        m1 += g_mom[k][b][1][c];
        m2 += g_mom[k][b][2][c];
        m3 += g_mom[k][b][3][c];
        m4 += g_mom[k][b][4][c];
    }

    const float s      = m0 + 1e-6f;
    const float inv_s  = 1.0f / s;
    const float mx     = m1 * inv_s;
    const float my     = m3 * inv_s;
    const float inv169s = inv_s * (1.0f / 169.0f);
    const float vx = (m2 - 2.0f * mx * m1 + mx * mx * m0) * inv169s;
    const float vy = (m4 - 2.0f * my * m3 + my * my * m0) * inv169s;
    const float t  = vx + vy;
    const float Z  = 17.079468445347132f;   // exp(log(2*pi) + 1) = 2*pi*e
    const float det = t * t * Z;

    __shared__ float rs[32];
    const int warp = c >> 5, lane = c & 31;
    float v = warp_sum(det);
    if (lane == 0) rs[warp] = v;
    __syncthreads();
    if (warp == 0) {
        float u = warp_sum(rs[lane]);
        if (lane == 0) g_partial[b] = u;
    }
}

// ---------------------------------------------------------------------------
// Kernel 3: final deterministic reduction over B -> scalar.
// ---------------------------------------------------------------------------
__global__ void final_kernel(float* __restrict__ out, int B) {
    const int tid  = threadIdx.x;
    const int warp = tid >> 5, lane = tid & 31;
    const int nwarps = (blockDim.x + 31) >> 5;

    float v = (tid < B) ? g_partial[tid] : 0.f;
    v = warp_sum(v);
    __shared__ float rs[32];
    if (lane == 0) rs[warp] = v;
    __syncthreads();
    if (warp == 0) {
        float u = (lane < nwarps) ? rs[lane] : 0.f;
        u = warp_sum(u);
        if (lane == 0) out[0] = u / ((float)B * (float)CCH);
    }
}

// ---------------------------------------------------------------------------
extern "C" void kernel_launch(void* const* d_in, const int* in_sizes, int n_in,
                              void* d_out, int out_size) {
    const float* x = (const float*)d_in[0];
    int B = in_sizes[0] / (HWD * HWD * CCH);   // 256
    if (B > BMAX) B = BMAX;

    dim3 grid(B, NCHUNK);
    moments_kernel<<<grid, CCH>>>(x);
    combine_kernel<<<B, CCH>>>();
    final_kernel<<<1, 256>>>((float*)d_out, B);
}

// round 6
// speedup vs baseline: 1.7091x; 1.7091x over previous
#include <cuda_runtime.h>

// ConstrainLoss: spatial-softmax moment loss.
// x: (B=256, 13, 13, C=1024) fp32. Output: scalar fp32.
//
// Per (b,h,w): f = softmax_c(x). Per (b,c): S0,S1x,S2x,S1y,S2y over 169 positions.
// var_x = (S2x - 2 mx S1x + mx^2 S0) / (169 (S0+eps)), mx = S1x/(S0+eps); same for y.
// det = (vx+vy)^2 * Z ; out = sum over (b,c) / (B*C).

#define CCH    1024
#define HWD    13
#define NCHUNK 4
#define BMAX   256
#define TPB    512      // moments kernel: 512 threads, 2 channels per thread

// Scratch: per-chunk partial moments [chunk][b][moment][c] (~21 MB) + per-b sums.
__device__ float g_mom[NCHUNK][BMAX][5][CCH];
__device__ float g_partial[BMAX];

__device__ __forceinline__ float warp_sum(float v) {
    v += __shfl_xor_sync(0xffffffffu, v, 16);
    v += __shfl_xor_sync(0xffffffffu, v, 8);
    v += __shfl_xor_sync(0xffffffffu, v, 4);
    v += __shfl_xor_sync(0xffffffffu, v, 2);
    v += __shfl_xor_sync(0xffffffffu, v, 1);
    return v;
}

// ---------------------------------------------------------------------------
// Kernel 1: per-(b, row-chunk) moment accumulation.
// grid = (B, 4); block = 512 threads, thread t owns channels (2t, 2t+1).
// chunk 0 -> rows 0..3, chunks 1..3 -> 3 rows each.
// Reduction: fold-by-2 shuffle + half-warp STS -> 13 warps finish via
// 2x LDS.128 + one butterfly. Two barriers per row.
// ---------------------------------------------------------------------------
__global__ __launch_bounds__(TPB, 2)
void moments_kernel(const float* __restrict__ x) {
    const int b     = blockIdx.x;
    const int chunk = blockIdx.y;
    const int h0    = (chunk == 0) ? 0 : (1 + 3 * chunk);   // 0,4,7,10
    const int nrows = (chunk == 0) ? 4 : 3;
    const int t     = threadIdx.x;
    const int warp  = t >> 5;
    const int lane  = t & 31;

    __shared__ float se[HWD][256];   // per-position staged partials (4-ch sums)
    __shared__ float s_inv[HWD];     // per-position 1/sum(exp)

    float2 s0  = {0.f, 0.f}, s1x = {0.f, 0.f}, s2x = {0.f, 0.f};
    float2 s1y = {0.f, 0.f}, s2y = {0.f, 0.f};

    for (int r = 0; r < nrows; ++r) {
        const int h = h0 + r;
        const float2* p =
            (const float2*)(x + (((size_t)b * HWD + h) * HWD) * CCH) + t;

        // 13 independent coalesced LDG.64 -> exp (no max-subtract: |x| < ~6)
        float2 e[HWD];
#pragma unroll
        for (int w = 0; w < HWD; ++w) {
            float2 v = __ldg(p + (size_t)w * (CCH / 2));
            e[w].x = __expf(v.x);
            e[w].y = __expf(v.y);
        }

        // Phase 1: thread-pair fold + half-warp store (16 partials per warp)
#pragma unroll
        for (int w = 0; w < HWD; ++w) {
            float v = e[w].x + e[w].y;
            v += __shfl_xor_sync(0xffffffffu, v, 16);
            if (lane < 16) se[w][(warp << 4) + lane] = v;
        }
        __syncthreads();

        // Phase 2: warps 0..12 each finish one position (256 partials)
        if (warp < HWD) {
            const float4* q = (const float4*)se[warp];
            float4 a = q[lane];
            float4 bq = q[lane + 32];
            float v = ((a.x + a.y) + (a.z + a.w)) +
                      ((bq.x + bq.y) + (bq.z + bq.w));
            v = warp_sum(v);
            if (lane == 0) s_inv[warp] = __frcp_rn(v);
        }
        __syncthreads();

        // Phase 3: accumulate moments. yv = w+1 compile-time immediates,
        // xv row-constant -> folded out of the inner loop.
        float2 r0 = {0.f, 0.f}, r1y = {0.f, 0.f}, r2y = {0.f, 0.f};
#pragma unroll
        for (int w = 0; w < HWD; ++w) {
            const float inv = s_inv[w];
            const float yv  = (float)(w + 1);
            const float gx  = e[w].x * inv;
            const float gy  = e[w].y * inv;
            r0.x += gx;                       r0.y += gy;
            r1y.x = fmaf(yv, gx, r1y.x);      r1y.y = fmaf(yv, gy, r1y.y);
            r2y.x = fmaf(yv * yv, gx, r2y.x); r2y.y = fmaf(yv * yv, gy, r2y.y);
        }
        const float xv = (float)(h + 1);
        s0.x  += r0.x;                        s0.y  += r0.y;
        s1x.x  = fmaf(xv, r0.x, s1x.x);       s1x.y  = fmaf(xv, r0.y, s1x.y);
        s2x.x  = fmaf(xv * xv, r0.x, s2x.x);  s2x.y  = fmaf(xv * xv, r0.y, s2x.y);
        s1y.x += r1y.x;                       s1y.y += r1y.y;
        s2y.x += r2y.x;                       s2y.y += r2y.y;
        // se/s_inv reuse is safe: phase-2 reads complete before the second
        // barrier; next row's writes come after it. s_inv reads (phase 3)
        // complete before the next row's first barrier.
    }

    float2* out = (float2*)&g_mom[chunk][b][0][0];
    out[0 * (CCH / 2) + t] = s0;
    out[1 * (CCH / 2) + t] = s1x;
    out[2 * (CCH / 2) + t] = s2x;
    out[3 * (CCH / 2) + t] = s1y;
    out[4 * (CCH / 2) + t] = s2y;
}

// ---------------------------------------------------------------------------
// Kernel 2: combine chunks, compute det per (b,c), reduce over c.
// grid = B, block = 1024.
// ---------------------------------------------------------------------------
__global__ __launch_bounds__(CCH)
void combine_kernel() {
    const int b = blockIdx.x;
    const int c = threadIdx.x;

    float m0 = 0.f, m1 = 0.f, m2 = 0.f, m3 = 0.f, m4 = 0.f;
#pragma unroll
    for (int k = 0; k < NCHUNK; ++k) {
        m0 += g_mom[k][b][0][c];
        m1 += g_mom[k][b][1][c];
        m2 += g_mom[k][b][2][c];
        m3 += g_mom[k][b][3][c];
        m4 += g_mom[k][b][4][c];
    }

    const float s       = m0 + 1e-6f;
    const float inv_s   = 1.0f / s;
    const float mx      = m1 * inv_s;
    const float my      = m3 * inv_s;
    const float inv169s = inv_s * (1.0f / 169.0f);
    const float vx = (m2 - 2.0f * mx * m1 + mx * mx * m0) * inv169s;
    const float vy = (m4 - 2.0f * my * m3 + my * my * m0) * inv169s;
    const float tt = vx + vy;
    const float Z  = 17.079468445347132f;   // exp(log(2*pi) + 1) = 2*pi*e
    const float det = tt * tt * Z;

    __shared__ float rs[32];
    const int warp = c >> 5, lane = c & 31;
    float v = warp_sum(det);
    if (lane == 0) rs[warp] = v;
    __syncthreads();
    if (warp == 0) {
        float u = warp_sum(rs[lane]);
        if (lane == 0) g_partial[b] = u;
    }
}

// ---------------------------------------------------------------------------
// Kernel 3: final deterministic reduction over B -> scalar.
// ---------------------------------------------------------------------------
__global__ void final_kernel(float* __restrict__ out, int B) {
    const int tid  = threadIdx.x;
    const int warp = tid >> 5, lane = tid & 31;
    const int nwarps = (blockDim.x + 31) >> 5;

    float v = (tid < B) ? g_partial[tid] : 0.f;
    v = warp_sum(v);
    __shared__ float rs[32];
    if (lane == 0) rs[warp] = v;
    __syncthreads();
    if (warp == 0) {
        float u = (lane < nwarps) ? rs[lane] : 0.f;
        u = warp_sum(u);
        if (lane == 0) out[0] = u / ((float)B * (float)CCH);
    }
}

// ---------------------------------------------------------------------------
extern "C" void kernel_launch(void* const* d_in, const int* in_sizes, int n_in,
                              void* d_out, int out_size) {
    const float* x = (const float*)d_in[0];
    int B = in_sizes[0] / (HWD * HWD * CCH);   // 256
    if (B > BMAX) B = BMAX;

    dim3 grid(B, NCHUNK);
    moments_kernel<<<grid, TPB>>>(x);
    combine_kernel<<<B, CCH>>>();
    final_kernel<<<1, 256>>>((float*)d_out, B);
}

// round 10
// speedup vs baseline: 1.9740x; 1.1550x over previous
#include <cuda_runtime.h>

// ConstrainLoss: spatial-softmax moment loss.
// x: (B=256, 13, 13, C=1024) fp32. Output: scalar fp32.
//
// Per (b,h,w): f = softmax_c(x). Per (b,c): S0,S1x,S2x,S1y,S2y over 169 positions.
// var_x = (S2x - 2 mx S1x + mx^2 S0) / (169 (S0+eps)), mx = S1x/(S0+eps); same y.
// det = (vx+vy)^2 * Z ; out = sum over (b,c) / (B*C).
//
// Fully fused: one block per batch element computes moments for all 169
// positions in registers, then det + channel reduction -> g_partial[b].
// Only a tiny final reduction kernel remains. Total HBM traffic = input only.

#define CCH  1024
#define HWD  13
#define BMAX 256
#define TPB  512      // 512 threads, thread t owns channels (2t, 2t+1)

__device__ float g_partial[BMAX];

__device__ __forceinline__ float warp_sum(float v) {
    v += __shfl_xor_sync(0xffffffffu, v, 16);
    v += __shfl_xor_sync(0xffffffffu, v, 8);
    v += __shfl_xor_sync(0xffffffffu, v, 4);
    v += __shfl_xor_sync(0xffffffffu, v, 2);
    v += __shfl_xor_sync(0xffffffffu, v, 1);
    return v;
}

// ---------------------------------------------------------------------------
// Kernel 1: fused per-batch moments + det + channel reduction.
// grid = B (256); block = 512, occ 2 -> all blocks co-resident (one wave).
// Per row: 13 coalesced LDG.64 -> exp -> staged two-level softmax-sum
// (fold-by-2 shuffle + half-warp STS; 13 warps finish via 2x LDS.128 +
//  one butterfly) -> register moment accumulation. 2 barriers per row.
// ---------------------------------------------------------------------------
__global__ __launch_bounds__(TPB, 2)
void fused_kernel(const float* __restrict__ x) {
    const int b    = blockIdx.x;
    const int t    = threadIdx.x;
    const int warp = t >> 5;
    const int lane = t & 31;

    __shared__ float se[HWD][256];   // per-position staged partials (4-ch sums)
    __shared__ float s_inv[HWD];     // per-position 1/sum(exp)

    float2 s0  = {0.f, 0.f}, s1x = {0.f, 0.f}, s2x = {0.f, 0.f};
    float2 s1y = {0.f, 0.f}, s2y = {0.f, 0.f};

    for (int h = 0; h < HWD; ++h) {
        const float2* p =
            (const float2*)(x + (((size_t)b * HWD + h) * HWD) * CCH) + t;

        // 13 independent coalesced LDG.64 -> exp (no max-subtract: |x| < ~6)
        float2 e[HWD];
#pragma unroll
        for (int w = 0; w < HWD; ++w) {
            float2 v = __ldg(p + (size_t)w * (CCH / 2));
            e[w].x = __expf(v.x);
            e[w].y = __expf(v.y);
        }

        // Phase 1: thread-pair fold + half-warp store (16 partials per warp)
#pragma unroll
        for (int w = 0; w < HWD; ++w) {
            float v = e[w].x + e[w].y;
            v += __shfl_xor_sync(0xffffffffu, v, 16);
            if (lane < 16) se[w][(warp << 4) + lane] = v;
        }
        __syncthreads();

        // Phase 2: warps 0..12 each finish one position (256 partials)
        if (warp < HWD) {
            const float4* q = (const float4*)se[warp];
            float4 a  = q[lane];
            float4 bq = q[lane + 32];
            float v = ((a.x + a.y) + (a.z + a.w)) +
                      ((bq.x + bq.y) + (bq.z + bq.w));
            v = warp_sum(v);
            if (lane == 0) s_inv[warp] = __frcp_rn(v);
        }
        __syncthreads();

        // Phase 3: accumulate moments. yv = w+1 compile-time immediates,
        // xv row-constant -> folded out of the inner loop.
        float2 r0 = {0.f, 0.f}, r1y = {0.f, 0.f}, r2y = {0.f, 0.f};
#pragma unroll
        for (int w = 0; w < HWD; ++w) {
            const float inv = s_inv[w];
            const float yv  = (float)(w + 1);
            const float gx  = e[w].x * inv;
            const float gy  = e[w].y * inv;
            r0.x += gx;                       r0.y += gy;
            r1y.x = fmaf(yv, gx, r1y.x);      r1y.y = fmaf(yv, gy, r1y.y);
            r2y.x = fmaf(yv * yv, gx, r2y.x); r2y.y = fmaf(yv * yv, gy, r2y.y);
        }
        const float xv = (float)(h + 1);
        s0.x  += r0.x;                        s0.y  += r0.y;
        s1x.x  = fmaf(xv, r0.x, s1x.x);       s1x.y  = fmaf(xv, r0.y, s1x.y);
        s2x.x  = fmaf(xv * xv, r0.x, s2x.x);  s2x.y  = fmaf(xv * xv, r0.y, s2x.y);
        s1y.x += r1y.x;                       s1y.y += r1y.y;
        s2y.x += r2y.x;                       s2y.y += r2y.y;
        // se/s_inv reuse is safe: phase-2 reads complete before the second
        // barrier; next row's writes come after it. s_inv reads (phase 3)
        // complete before the next row's first barrier.
    }

    // ---- Epilogue: det per channel, reduce over the block ----
    const float Z = 17.079468445347132f;   // exp(log(2*pi) + 1) = 2*pi*e
    float dsum;
    {
        // channel .x
        float s      = s0.x + 1e-6f;
        float inv_s  = 1.0f / s;
        float mx     = s1x.x * inv_s;
        float my     = s1y.x * inv_s;
        float inv169 = inv_s * (1.0f / 169.0f);
        float vx = (s2x.x - 2.0f * mx * s1x.x + mx * mx * s0.x) * inv169;
        float vy = (s2y.x - 2.0f * my * s1y.x + my * my * s0.x) * inv169;
        float tt = vx + vy;
        dsum = tt * tt * Z;
    }
    {
        // channel .y
        float s      = s0.y + 1e-6f;
        float inv_s  = 1.0f / s;
        float mx     = s1x.y * inv_s;
        float my     = s1y.y * inv_s;
        float inv169 = inv_s * (1.0f / 169.0f);
        float vx = (s2x.y - 2.0f * mx * s1x.y + mx * mx * s0.y) * inv169;
        float vy = (s2y.y - 2.0f * my * s1y.y + my * my * s0.y) * inv169;
        float tt = vx + vy;
        dsum += tt * tt * Z;
    }

    __shared__ float rs[16];
    float v = warp_sum(dsum);
    if (lane == 0) rs[warp] = v;
    __syncthreads();
    if (warp == 0) {
        float u = (lane < 16) ? rs[lane] : 0.f;
        u = warp_sum(u);
        if (lane == 0) g_partial[b] = u;
    }
}

// ---------------------------------------------------------------------------
// Kernel 2: final deterministic reduction over B -> scalar.
// ---------------------------------------------------------------------------
__global__ void final_kernel(float* __restrict__ out, int B) {
    const int tid  = threadIdx.x;
    const int warp = tid >> 5, lane = tid & 31;
    const int nwarps = (blockDim.x + 31) >> 5;

    float v = (tid < B) ? g_partial[tid] : 0.f;
    v = warp_sum(v);
    __shared__ float rs[32];
    if (lane == 0) rs[warp] = v;
    __syncthreads();
    if (warp == 0) {
        float u = (lane < nwarps) ? rs[lane] : 0.f;
        u = warp_sum(u);
        if (lane == 0) out[0] = u / ((float)B * (float)CCH);
    }
}

// ---------------------------------------------------------------------------
extern "C" void kernel_launch(void* const* d_in, const int* in_sizes, int n_in,
                              void* d_out, int out_size) {
    const float* x = (const float*)d_in[0];
    int B = in_sizes[0] / (HWD * HWD * CCH);   // 256
    if (B > BMAX) B = BMAX;

    fused_kernel<<<B, TPB>>>(x);
    final_kernel<<<1, 256>>>((float*)d_out, B);
}